// round 6
// baseline (speedup 1.0000x reference)
#include <cuda_runtime.h>
#include <cuda_fp16.h>
#include <mma.h>
#include <cstdint>

using namespace nvcuda;

// ---------------- problem constants ----------------
#define BATCH   256
#define INSTRS  64
#define TOKENS  16
#define HID     256
#define EMB     256
#define FOURH   1024
#define KTOT    512
#define NTOK    (BATCH*INSTRS)   // 16384

// ---------------- GEMM tile config (fp16 m16n16k16, 3-stage cp.async) ----------------
#define BM 128
#define BN 64
#define BK 64
#define LDSH 72                  // BK + 8 pad (half; rows 144B, 16B aligned)
#define NK  (KTOT/BK)            // 8
#define CLD 68                   // epilogue Cs stride (floats)

// dynamic smem layout (bytes):
//  As: [3][BM*LDSH] half = 55296 @ 0      (Cs float[128][68]=34816 overlays)
//  Bs: [3][BN*LDSH] half = 27648 @ 55296
//  Aidx: int[128]           @ 82944
//  Arow: ptr[128]           @ 83456
#define AS_OFF   0
#define BS_OFF   55296
#define AIDX_OFF 82944
#define AROW_OFF 83456
#define SMEM_BYTES 84480

#define INS_BLOCKS 32            // persistent instr-phase grid

// ---------------- device state ----------------
// h ping-ponged by step parity: step t reads h[(t&1)^1], writes h[t&1].
__device__ __half g_h_tok[2][(size_t)NTOK * HID];
__device__ float  g_c_tok[(size_t)NTOK * HID];
__device__ __half g_h_ins[2][(size_t)BATCH * HID];
__device__ float  g_c_ins[(size_t)BATCH * HID];
__device__ __half g_instr_repr[(size_t)NTOK * HID];
__device__ int    g_perm_tok[NTOK];
__device__ int    g_cnt_tok[TOKENS];
__device__ int    g_perm_ins[BATCH];
__device__ int    g_cnt_ins[INSTRS];
__device__ volatile unsigned g_bar;           // persistent-kernel grid barrier
// pre-converted fp16 operands
__device__ __half g_emb_h[(size_t)4096 * EMB];
__device__ __half g_W_tok[(size_t)FOURH * KTOT];   // [jp][512], gate-interleaved rows
__device__ __half g_W_ins[(size_t)FOURH * KTOT];

#define CP_ASYNC16(dst, src) \
    asm volatile("cp.async.cg.shared.global [%0], [%1], 16;" :: "r"(dst), "l"(src))
#define CP_COMMIT  asm volatile("cp.async.commit_group;")
#define CP_WAIT0   asm volatile("cp.async.wait_group 0;")
#define CP_WAIT1   asm volatile("cp.async.wait_group 1;")

// ---- shared per-block LSTM tile step: gate-interleaved GEMM + cell update ----
template<int MODE>
__device__ __forceinline__ void
tile_step(int t, int m0, int n0, char* smraw,
          const int* __restrict__ tok,
          const float* __restrict__ bias,
          const int* __restrict__ len_arr)
{
    __half*        As   = (__half*)(smraw + AS_OFF);
    __half*        Bs   = (__half*)(smraw + BS_OFF);
    int*           Aidx = (int*)(smraw + AIDX_OFF);
    const __half** Arow = (const __half**)(smraw + AROW_OFF);
    float*         Cs   = (float*)smraw;   // overlay (post-mainloop only)

    const int tid = threadIdx.x;
    const int wp  = t & 1;
    const int rp  = wp ^ 1;

    const int*    perm  = (MODE == 0) ? g_perm_tok : g_perm_ins;
    const __half* hbase = (MODE == 0) ? g_h_tok[rp] : g_h_ins[rp];
    const __half* Wbuf  = (MODE == 0) ? g_W_tok : g_W_ins;

    for (int r = tid; r < BM; r += 256) {
        int n = perm[m0 + r];
        Aidx[r] = n;
        if (MODE == 0)
            Arow[r] = g_emb_h + (size_t)__ldg(&tok[n * TOKENS + t]) * EMB;
        else
            Arow[r] = g_instr_repr + ((size_t)n * INSTRS + t) * HID;
    }
    __syncthreads();

    auto issue = [&](int kt, int buf) {
        __half* Ad = As + buf * BM * LDSH;
#pragma unroll
        for (int i = 0; i < 4; ++i) {
            int c  = tid + i * 256;
            int r  = c >> 3;
            int c8 = (c & 7) << 3;
            const __half* src = (kt < 4)
                ? Arow[r] + kt * BK + c8
                : hbase + (size_t)Aidx[r] * HID + (kt - 4) * BK + c8;
            uint32_t dst = (uint32_t)__cvta_generic_to_shared(Ad + r * LDSH + c8);
            CP_ASYNC16(dst, src);
        }
        __half* Bd = Bs + buf * BN * LDSH;
#pragma unroll
        for (int i = 0; i < 2; ++i) {
            int c  = tid + i * 256;
            int r  = c >> 3;
            int c8 = (c & 7) << 3;
            const __half* src = Wbuf + (size_t)(n0 + r) * KTOT + kt * BK + c8;
            uint32_t dst = (uint32_t)__cvta_generic_to_shared(Bd + r * LDSH + c8);
            CP_ASYNC16(dst, src);
        }
        CP_COMMIT;
    };

    wmma::fragment<wmma::accumulator, 16, 16, 16, float> cf[2][2];
#pragma unroll
    for (int mi = 0; mi < 2; ++mi)
#pragma unroll
        for (int ni = 0; ni < 2; ++ni)
            wmma::fill_fragment(cf[mi][ni], 0.0f);

    const int warp = tid >> 5;
    const int wm   = warp >> 1;   // 0..3: 32-row slice
    const int wn   = warp & 1;    // 0..1: 32-col slice

    issue(0, 0);
    issue(1, 1);
    for (int kt = 0; kt < NK; ++kt) {
        if (kt < NK - 2) { CP_WAIT1; } else { CP_WAIT0; }
        __syncthreads();
        if (kt + 2 < NK) issue(kt + 2, (kt + 2) % 3);
        const __half* Ab = As + (kt % 3) * BM * LDSH;
        const __half* Bb = Bs + (kt % 3) * BN * LDSH;
#pragma unroll
        for (int kk = 0; kk < BK; kk += 16) {
            wmma::fragment<wmma::matrix_a, 16, 16, 16, __half, wmma::row_major> a[2];
            wmma::fragment<wmma::matrix_b, 16, 16, 16, __half, wmma::col_major> b[2];
#pragma unroll
            for (int mi = 0; mi < 2; ++mi)
                wmma::load_matrix_sync(a[mi], Ab + (wm * 32 + mi * 16) * LDSH + kk, LDSH);
#pragma unroll
            for (int ni = 0; ni < 2; ++ni)
                wmma::load_matrix_sync(b[ni], Bb + (wn * 32 + ni * 16) * LDSH + kk, LDSH);
#pragma unroll
            for (int mi = 0; mi < 2; ++mi)
#pragma unroll
                for (int ni = 0; ni < 2; ++ni)
                    wmma::mma_sync(cf[mi][ni], a[mi], b[ni], cf[mi][ni]);
        }
    }

    // ---- epilogue: stage gates, apply cell update ----
    __syncthreads();
#pragma unroll
    for (int mi = 0; mi < 2; ++mi)
#pragma unroll
        for (int ni = 0; ni < 2; ++ni)
            wmma::store_matrix_sync(&Cs[(wm * 32 + mi * 16) * CLD + wn * 32 + ni * 16],
                                    cf[mi][ni], CLD, wmma::mem_row_major);
    __syncthreads();

    {
        int r = tid >> 1;
        int n = Aidx[r];
        int L = __ldg(&len_arr[n]);
        if (t < L) {
            __half* hp = (MODE == 0) ? g_h_tok[wp] : g_h_ins[wp];
            float*  cp = (MODE == 0) ? g_c_tok : g_c_ins;
            int dg0 = (n0 >> 2) + (tid & 1) * 8;
#pragma unroll
            for (int i = 0; i < 8; ++i) {
                int dl = (tid & 1) * 8 + i;
                int dg = dg0 + i;
                float gi = Cs[r * CLD + dl * 4 + 0] + __ldg(&bias[dg]);
                float gf = Cs[r * CLD + dl * 4 + 1] + __ldg(&bias[256 + dg]);
                float gg = Cs[r * CLD + dl * 4 + 2] + __ldg(&bias[512 + dg]);
                float go = Cs[r * CLD + dl * 4 + 3] + __ldg(&bias[768 + dg]);
                float i_ = 1.0f / (1.0f + expf(-gi));
                float f_ = 1.0f / (1.0f + expf(-gf));
                float g_ = tanhf(gg);
                float o_ = 1.0f / (1.0f + expf(-go));
                size_t idx = (size_t)n * HID + dg;
                float cn = f_ * cp[idx] + i_ * g_;
                cp[idx] = cn;
                hp[idx] = __float2half_rn(o_ * tanhf(cn));
            }
        }
    }
    __syncthreads();   // smem (Cs/As overlay) safe for reuse by caller's next step
}

// ---- token phase: one launch per step, blocks self-trim via compaction ----
__global__ void __launch_bounds__(256)
tok_step(int t, const int* __restrict__ tok,
         const float* __restrict__ bias, const int* __restrict__ ntok)
{
    if (blockIdx.x * BM >= g_cnt_tok[t]) return;
    extern __shared__ char smraw[];
    tile_step<0>(t, blockIdx.x * BM, blockIdx.y * BN, smraw, tok, bias, ntok);
}

// ---- instr phase: ONE persistent launch, software grid barrier between steps ----
__device__ __forceinline__ void grid_bar(int step)
{
    __syncthreads();
    if (threadIdx.x == 0) {
        __threadfence();                      // release our block's writes
        atomicAdd((unsigned*)&g_bar, 1u);
        unsigned target = (unsigned)INS_BLOCKS * (step + 1);
        while (g_bar < target) { }
        __threadfence();                      // acquire other blocks' writes
    }
    __syncthreads();
}

__global__ void __launch_bounds__(256)
instr_persist(const float* __restrict__ bias, const int* __restrict__ ninstr)
{
    extern __shared__ char smraw[];
    const int bx = blockIdx.x & 1;        // m-tile (0..1)
    const int by = blockIdx.x >> 1;       // n-tile (0..15)
    for (int s = 0; s < INSTRS; ++s) {
        if (bx * BM < g_cnt_ins[s])
            tile_step<1>(s, bx * BM, by * BN, smraw, nullptr, bias, ninstr);
        grid_bar(s);                      // all blocks participate every step
    }
}

// gather final token-phase h from the parity buffer of each row's last step
__global__ void __launch_bounds__(256)
gather_tok(const int* __restrict__ ntok)
{
    int idx = blockIdx.x * 256 + threadIdx.x;   // over NTOK*HID
    int n = idx >> 8;
    int L = ntok[n];
    g_instr_repr[idx] = (L > 0) ? g_h_tok[(L - 1) & 1][idx] : __half(0.0f);
}

// convert weights into gate-interleaved fp16 [jp][512]
__global__ void __launch_bounds__(256)
prep_weights(const float* __restrict__ WihT, const float* __restrict__ WhhT,
             const float* __restrict__ WihI, const float* __restrict__ WhhI)
{
    int idx = blockIdx.x * 256 + threadIdx.x;   // over 1024*512
    int jp = idx >> 9;
    int k  = idx & 511;
    int j  = (jp & 3) * 256 + (jp >> 2);        // gate*256 + d
    float v = (k < 256) ? WihT[j * 256 + k] : WhhT[j * 256 + (k - 256)];
    g_W_tok[idx] = __float2half_rn(v);
    float u = (k < 256) ? WihI[j * 256 + k] : WhhI[j * 256 + (k - 256)];
    g_W_ins[idx] = __float2half_rn(u);
}

__global__ void __launch_bounds__(256)
prep_emb(const float* __restrict__ emb)
{
    int idx = blockIdx.x * 256 + threadIdx.x;   // over 4096*256
    g_emb_h[idx] = __float2half_rn(emb[idx]);
}

// counting sort by length (descending) + active-count table
__global__ void build_perm(const int* __restrict__ ntok,
                           const int* __restrict__ ninstr)
{
    __shared__ int hist[65];
    __shared__ int off[65];
    if (blockIdx.x == 0) {
        for (int i = threadIdx.x; i < 17; i += blockDim.x) hist[i] = 0;
        __syncthreads();
        for (int i = threadIdx.x; i < NTOK; i += blockDim.x)
            atomicAdd(&hist[ntok[i]], 1);
        __syncthreads();
        if (threadIdx.x == 0) {
            int acc = 0;
            for (int l = 16; l >= 0; --l) { off[l] = acc; acc += hist[l]; }
            for (int t = 0; t < TOKENS; ++t) g_cnt_tok[t] = off[t];
        }
        __syncthreads();
        for (int i = threadIdx.x; i < NTOK; i += blockDim.x) {
            int p = atomicAdd(&off[ntok[i]], 1);
            g_perm_tok[p] = i;
        }
    } else {
        for (int i = threadIdx.x; i < 65; i += blockDim.x) hist[i] = 0;
        __syncthreads();
        for (int i = threadIdx.x; i < BATCH; i += blockDim.x)
            atomicAdd(&hist[ninstr[i]], 1);
        __syncthreads();
        if (threadIdx.x == 0) {
            int acc = 0;
            for (int l = 64; l >= 0; --l) { off[l] = acc; acc += hist[l]; }
            for (int s = 0; s < INSTRS; ++s) g_cnt_ins[s] = off[s];
        }
        __syncthreads();
        for (int i = threadIdx.x; i < BATCH; i += blockDim.x) {
            int p = atomicAdd(&off[ninstr[i]], 1);
            g_perm_ins[p] = i;
        }
    }
}

__global__ void __launch_bounds__(256) zero_state()
{
    int idx = blockIdx.x * 256 + threadIdx.x;   // grid covers NTOK*HID
    g_h_tok[0][idx] = __half(0.0f);
    g_h_tok[1][idx] = __half(0.0f);
    g_c_tok[idx]    = 0.0f;
    if (idx < BATCH * HID) {
        g_h_ins[0][idx] = __half(0.0f);
        g_h_ins[1][idx] = __half(0.0f);
        g_c_ins[idx]    = 0.0f;
    }
    if (idx == 0) g_bar = 0u;                   // reset persistent-kernel barrier
}

__global__ void __launch_bounds__(256)
final_linear(const int* __restrict__ ninstr,
             const float* __restrict__ linW,
             const float* __restrict__ linb,
             float* __restrict__ out)
{
    int b = blockIdx.x, tid = threadIdx.x;
    int L = ninstr[b];
    float h = (L > 0) ? __half2float(g_h_ins[(L - 1) & 1][(size_t)b * HID + tid]) : 0.0f;
    float v = h * linW[tid];
#pragma unroll
    for (int o = 16; o > 0; o >>= 1) v += __shfl_down_sync(0xffffffffu, v, o);
    __shared__ float red[8];
    if ((tid & 31) == 0) red[tid >> 5] = v;
    __syncthreads();
    if (tid < 8) {
        float s = red[tid];
#pragma unroll
        for (int o = 4; o > 0; o >>= 1) s += __shfl_down_sync(0xffu, s, o);
        if (tid == 0) out[b] = s + linb[0];
    }
}

extern "C" void kernel_launch(void* const* d_in, const int* in_sizes, int n_in,
                              void* d_out, int out_size)
{
    const int*   blocks = (const int*)d_in[0];
    const int*   ninstr = (const int*)d_in[1];
    const int*   ntok   = (const int*)d_in[2];
    const float* emb    = (const float*)d_in[3];
    const float* WihT   = (const float*)d_in[4];
    const float* WhhT   = (const float*)d_in[5];
    const float* bT     = (const float*)d_in[6];
    const float* WihI   = (const float*)d_in[7];
    const float* WhhI   = (const float*)d_in[8];
    const float* bI     = (const float*)d_in[9];
    const float* linW   = (const float*)d_in[10];
    const float* linb   = (const float*)d_in[11];
    float* out = (float*)d_out;
    (void)in_sizes; (void)n_in; (void)out_size;

    cudaFuncSetAttribute(tok_step,      cudaFuncAttributeMaxDynamicSharedMemorySize, SMEM_BYTES);
    cudaFuncSetAttribute(instr_persist, cudaFuncAttributeMaxDynamicSharedMemorySize, SMEM_BYTES);

    zero_state<<<NTOK * HID / 256, 256>>>();
    build_perm<<<2, 512>>>(ntok, ninstr);
    prep_weights<<<FOURH * KTOT / 256, 256>>>(WihT, WhhT, WihI, WhhI);
    prep_emb<<<4096 * EMB / 256, 256>>>(emb);

    for (int t = 0; t < TOKENS; ++t) {
        dim3 grid(NTOK / BM, FOURH / BN);          // 128 x 16, blocks self-trim
        tok_step<<<grid, 256, SMEM_BYTES>>>(t, blocks, bT, ntok);
    }
    gather_tok<<<NTOK * HID / 256, 256>>>(ntok);
    instr_persist<<<INS_BLOCKS, 256, SMEM_BYTES>>>(bI, ninstr);
    final_linear<<<BATCH, 256>>>(ninstr, linW, linb, out);
}

// round 7
// speedup vs baseline: 1.0049x; 1.0049x over previous
#include <cuda_runtime.h>
#include <cuda_fp16.h>
#include <mma.h>
#include <cstdint>

using namespace nvcuda;

// ---------------- problem constants ----------------
#define BATCH   256
#define INSTRS  64
#define TOKENS  16
#define HID     256
#define EMB     256
#define FOURH   1024
#define KTOT    512
#define NTOK    (BATCH*INSTRS)   // 16384

// ---------------- token GEMM tile config (fp16 m16n16k16, 2-stage) ----------------
#define BM 128
#define BN 64
#define BK 64
#define LDSH 72                  // BK + 8 pad
#define NK  (KTOT/BK)            // 8
#define CLD 68                   // epilogue Cs stride (floats)

// token kernel smem (bytes): As[2][128*72]h=36864 @0 (Cs overlays), Bs[2][64*72]h=18432 @36864,
// Aidx @55296 (512), Arow @55808 (1024)
#define SMEM_TOK 56832

// ---------------- instr persistent kernel ----------------
#define INS_BLOCKS 32
// smem: W[64][520]h = 66560 @0 ; A[2][128][72]h = 36864 @66560 (Cs overlays A) ; Aidx @103424
#define LDW      520
#define IW_OFF   0
#define IA_OFF   66560
#define IIDX_OFF 103424
#define SMEM_INS 103936

// ---------------- device state ----------------
// h ping-ponged by step parity: step t reads h[(t&1)^1], writes h[t&1].
__device__ __half g_h_tok[2][(size_t)NTOK * HID];
__device__ float  g_c_tok[(size_t)NTOK * HID];
__device__ __half g_h_ins[2][(size_t)BATCH * HID];
__device__ float  g_c_ins[(size_t)BATCH * HID];
__device__ __half g_instr_repr[(size_t)NTOK * HID];
__device__ int    g_perm_tok[NTOK];
__device__ int    g_cnt_tok[TOKENS];
__device__ int    g_perm_ins[BATCH];
__device__ int    g_cnt_ins[INSTRS];
__device__ volatile unsigned g_bar;
// pre-converted fp16 operands
__device__ __half g_emb_h[(size_t)4096 * EMB];
__device__ __half g_W_tok[(size_t)FOURH * KTOT];   // [jp][512], gate-interleaved
__device__ __half g_W_ins[(size_t)FOURH * KTOT];

#define CP_ASYNC16(dst, src) \
    asm volatile("cp.async.cg.shared.global [%0], [%1], 16;" :: "r"(dst), "l"(src))
#define CP_COMMIT  asm volatile("cp.async.commit_group;")
#define CP_WAIT0   asm volatile("cp.async.wait_group 0;")

// ================= token phase: round-5 proven fused step =================
__global__ void __launch_bounds__(256)
tok_step(int t, const int* __restrict__ tok,
         const float* __restrict__ bias, const int* __restrict__ ntok)
{
    if (blockIdx.x * BM >= g_cnt_tok[t]) return;

    extern __shared__ char smraw[];
    __half*        As   = (__half*)smraw;
    __half*        Bs   = (__half*)(smraw + 36864);
    int*           Aidx = (int*)(smraw + 55296);
    const __half** Arow = (const __half**)(smraw + 55808);
    float*         Cs   = (float*)smraw;   // overlay

    const int m0  = blockIdx.x * BM;
    const int n0  = blockIdx.y * BN;
    const int tid = threadIdx.x;
    const int wp  = t & 1;
    const int rp  = wp ^ 1;

    const __half* hbase = g_h_tok[rp];

    for (int r = tid; r < BM; r += 256) {
        int n = g_perm_tok[m0 + r];
        Aidx[r] = n;
        Arow[r] = g_emb_h + (size_t)__ldg(&tok[n * TOKENS + t]) * EMB;
    }
    __syncthreads();

    auto issue = [&](int kt, int buf) {
        __half* Ad = As + buf * BM * LDSH;
#pragma unroll
        for (int i = 0; i < 4; ++i) {
            int c  = tid + i * 256;
            int r  = c >> 3;
            int c8 = (c & 7) << 3;
            const __half* src = (kt < 4)
                ? Arow[r] + kt * BK + c8
                : hbase + (size_t)Aidx[r] * HID + (kt - 4) * BK + c8;
            uint32_t dst = (uint32_t)__cvta_generic_to_shared(Ad + r * LDSH + c8);
            CP_ASYNC16(dst, src);
        }
        __half* Bd = Bs + buf * BN * LDSH;
#pragma unroll
        for (int i = 0; i < 2; ++i) {
            int c  = tid + i * 256;
            int r  = c >> 3;
            int c8 = (c & 7) << 3;
            const __half* src = g_W_tok + (size_t)(n0 + r) * KTOT + kt * BK + c8;
            uint32_t dst = (uint32_t)__cvta_generic_to_shared(Bd + r * LDSH + c8);
            CP_ASYNC16(dst, src);
        }
        CP_COMMIT;
    };

    wmma::fragment<wmma::accumulator, 16, 16, 16, float> cf[2][2];
#pragma unroll
    for (int mi = 0; mi < 2; ++mi)
#pragma unroll
        for (int ni = 0; ni < 2; ++ni)
            wmma::fill_fragment(cf[mi][ni], 0.0f);

    const int warp = tid >> 5;
    const int wm   = warp >> 1;
    const int wn   = warp & 1;

    issue(0, 0);
    for (int kt = 0; kt < NK; ++kt) {
        CP_WAIT0;
        __syncthreads();
        if (kt + 1 < NK) issue(kt + 1, (kt + 1) & 1);
        const __half* Ab = As + (kt & 1) * BM * LDSH;
        const __half* Bb = Bs + (kt & 1) * BN * LDSH;
#pragma unroll
        for (int kk = 0; kk < BK; kk += 16) {
            wmma::fragment<wmma::matrix_a, 16, 16, 16, __half, wmma::row_major> a[2];
            wmma::fragment<wmma::matrix_b, 16, 16, 16, __half, wmma::col_major> b[2];
#pragma unroll
            for (int mi = 0; mi < 2; ++mi)
                wmma::load_matrix_sync(a[mi], Ab + (wm * 32 + mi * 16) * LDSH + kk, LDSH);
#pragma unroll
            for (int ni = 0; ni < 2; ++ni)
                wmma::load_matrix_sync(b[ni], Bb + (wn * 32 + ni * 16) * LDSH + kk, LDSH);
#pragma unroll
            for (int mi = 0; mi < 2; ++mi)
#pragma unroll
                for (int ni = 0; ni < 2; ++ni)
                    wmma::mma_sync(cf[mi][ni], a[mi], b[ni], cf[mi][ni]);
        }
    }

    __syncthreads();
#pragma unroll
    for (int mi = 0; mi < 2; ++mi)
#pragma unroll
        for (int ni = 0; ni < 2; ++ni)
            wmma::store_matrix_sync(&Cs[(wm * 32 + mi * 16) * CLD + wn * 32 + ni * 16],
                                    cf[mi][ni], CLD, wmma::mem_row_major);
    __syncthreads();

    {
        int r = tid >> 1;
        int n = Aidx[r];
        int L = __ldg(&ntok[n]);
        if (t < L) {
            __half* hp = g_h_tok[wp];
            float*  cp = g_c_tok;
            int dg0 = (n0 >> 2) + (tid & 1) * 8;
#pragma unroll
            for (int i = 0; i < 8; ++i) {
                int dl = (tid & 1) * 8 + i;
                int dg = dg0 + i;
                float gi = Cs[r * CLD + dl * 4 + 0] + __ldg(&bias[dg]);
                float gf = Cs[r * CLD + dl * 4 + 1] + __ldg(&bias[256 + dg]);
                float gg = Cs[r * CLD + dl * 4 + 2] + __ldg(&bias[512 + dg]);
                float go = Cs[r * CLD + dl * 4 + 3] + __ldg(&bias[768 + dg]);
                float i_ = 1.0f / (1.0f + expf(-gi));
                float f_ = 1.0f / (1.0f + expf(-gf));
                float g_ = tanhf(gg);
                float o_ = 1.0f / (1.0f + expf(-go));
                size_t idx = (size_t)n * HID + dg;
                float cn = f_ * cp[idx] + i_ * g_;
                cp[idx] = cn;
                hp[idx] = __float2half_rn(o_ * tanhf(cn));
            }
        }
    }
}

// ================= instr phase: ONE persistent launch, W resident in smem =================
__device__ __forceinline__ void grid_bar(int step)
{
    __syncthreads();
    if (threadIdx.x == 0) {
        __threadfence();
        atomicAdd((unsigned*)&g_bar, 1u);
        unsigned target = (unsigned)INS_BLOCKS * (step + 1);
        while (g_bar < target) { }
        __threadfence();
    }
    __syncthreads();
}

__global__ void __launch_bounds__(256)
instr_persist(const float* __restrict__ bias, const int* __restrict__ ninstr)
{
    extern __shared__ char smraw[];
    __half* Ws   = (__half*)(smraw + IW_OFF);     // [64][LDW]
    __half* As   = (__half*)(smraw + IA_OFF);     // [2][128][LDSH]
    int*    Aidx = (int*)(smraw + IIDX_OFF);
    float*  Cs   = (float*)(smraw + IA_OFF);      // overlay on A (post-mainloop)

    const int tid = threadIdx.x;
    const int bx  = blockIdx.x & 1;               // m-tile
    const int by  = blockIdx.x >> 1;              // n-tile 0..15
    const int m0  = bx * BM;
    const int n0  = by * BN;

    // one-time: W slice into smem (64 rows x 512 halfs), Aidx (perm is static)
#pragma unroll
    for (int i = 0; i < 16; ++i) {
        int c  = tid + i * 256;                   // 0..4095 chunks of 8 halfs
        int r  = c >> 6;
        int c8 = (c & 63) << 3;
        uint32_t dst = (uint32_t)__cvta_generic_to_shared(Ws + r * LDW + c8);
        CP_ASYNC16(dst, g_W_ins + (size_t)(n0 + r) * KTOT + c8);
    }
    CP_COMMIT;
    for (int r = tid; r < BM; r += 256) Aidx[r] = g_perm_ins[m0 + r];
    CP_WAIT0;
    __syncthreads();

    const int warp = tid >> 5;
    const int wm   = warp >> 1;
    const int wn   = warp & 1;

    for (int s = 0; s < INSTRS; ++s) {
        if (m0 < g_cnt_ins[s]) {
            const int wp = s & 1;
            const int rp = wp ^ 1;
            const __half* hbase = g_h_ins[rp];

            auto issueA = [&](int kt, int buf) {
                __half* Ad = As + buf * BM * LDSH;
#pragma unroll
                for (int i = 0; i < 4; ++i) {
                    int c  = tid + i * 256;
                    int r  = c >> 3;
                    int c8 = (c & 7) << 3;
                    int n  = Aidx[r];
                    const __half* src = (kt < 4)
                        ? g_instr_repr + ((size_t)n * INSTRS + s) * HID + kt * BK + c8
                        : hbase + (size_t)n * HID + (kt - 4) * BK + c8;
                    uint32_t dst = (uint32_t)__cvta_generic_to_shared(Ad + r * LDSH + c8);
                    CP_ASYNC16(dst, src);
                }
                CP_COMMIT;
            };

            wmma::fragment<wmma::accumulator, 16, 16, 16, float> cf[2][2];
#pragma unroll
            for (int mi = 0; mi < 2; ++mi)
#pragma unroll
                for (int ni = 0; ni < 2; ++ni)
                    wmma::fill_fragment(cf[mi][ni], 0.0f);

            issueA(0, 0);
            for (int kt = 0; kt < NK; ++kt) {
                CP_WAIT0;
                __syncthreads();
                if (kt + 1 < NK) issueA(kt + 1, (kt + 1) & 1);
                const __half* Ab = As + (kt & 1) * BM * LDSH;
                const __half* Wb = Ws + kt * BK;          // [n][k] within resident W
#pragma unroll
                for (int kk = 0; kk < BK; kk += 16) {
                    wmma::fragment<wmma::matrix_a, 16, 16, 16, __half, wmma::row_major> a[2];
                    wmma::fragment<wmma::matrix_b, 16, 16, 16, __half, wmma::col_major> b[2];
#pragma unroll
                    for (int mi = 0; mi < 2; ++mi)
                        wmma::load_matrix_sync(a[mi], Ab + (wm * 32 + mi * 16) * LDSH + kk, LDSH);
#pragma unroll
                    for (int ni = 0; ni < 2; ++ni)
                        wmma::load_matrix_sync(b[ni], Wb + (wn * 32 + ni * 16) * LDW + kk, LDW);
#pragma unroll
                    for (int mi = 0; mi < 2; ++mi)
#pragma unroll
                        for (int ni = 0; ni < 2; ++ni)
                            wmma::mma_sync(cf[mi][ni], a[mi], b[ni], cf[mi][ni]);
                }
            }

            __syncthreads();
#pragma unroll
            for (int mi = 0; mi < 2; ++mi)
#pragma unroll
                for (int ni = 0; ni < 2; ++ni)
                    wmma::store_matrix_sync(&Cs[(wm * 32 + mi * 16) * CLD + wn * 32 + ni * 16],
                                            cf[mi][ni], CLD, wmma::mem_row_major);
            __syncthreads();

            {
                int r = tid >> 1;
                int n = Aidx[r];
                int L = __ldg(&ninstr[n]);
                if (s < L) {
                    __half* hp = g_h_ins[wp];
                    float*  cp = g_c_ins;
                    int dg0 = (n0 >> 2) + (tid & 1) * 8;
#pragma unroll
                    for (int i = 0; i < 8; ++i) {
                        int dl = (tid & 1) * 8 + i;
                        int dg = dg0 + i;
                        float gi = Cs[r * CLD + dl * 4 + 0] + __ldg(&bias[dg]);
                        float gf = Cs[r * CLD + dl * 4 + 1] + __ldg(&bias[256 + dg]);
                        float gg = Cs[r * CLD + dl * 4 + 2] + __ldg(&bias[512 + dg]);
                        float go = Cs[r * CLD + dl * 4 + 3] + __ldg(&bias[768 + dg]);
                        float i_ = 1.0f / (1.0f + expf(-gi));
                        float f_ = 1.0f / (1.0f + expf(-gf));
                        float g_ = tanhf(gg);
                        float o_ = 1.0f / (1.0f + expf(-go));
                        size_t idx = (size_t)n * HID + dg;
                        float cn = f_ * cp[idx] + i_ * g_;
                        cp[idx] = cn;
                        hp[idx] = __float2half_rn(o_ * tanhf(cn));
                    }
                }
            }
        }
        grid_bar(s);
    }
}

// gather final token-phase h from the parity buffer of each row's last step
__global__ void __launch_bounds__(256)
gather_tok(const int* __restrict__ ntok)
{
    int idx = blockIdx.x * 256 + threadIdx.x;
    int n = idx >> 8;
    int L = ntok[n];
    g_instr_repr[idx] = (L > 0) ? g_h_tok[(L - 1) & 1][idx] : __half(0.0f);
}

// convert weights into gate-interleaved fp16 [jp][512]
__global__ void __launch_bounds__(256)
prep_weights(const float* __restrict__ WihT, const float* __restrict__ WhhT,
             const float* __restrict__ WihI, const float* __restrict__ WhhI)
{
    int idx = blockIdx.x * 256 + threadIdx.x;
    int jp = idx >> 9;
    int k  = idx & 511;
    int j  = (jp & 3) * 256 + (jp >> 2);
    float v = (k < 256) ? WihT[j * 256 + k] : WhhT[j * 256 + (k - 256)];
    g_W_tok[idx] = __float2half_rn(v);
    float u = (k < 256) ? WihI[j * 256 + k] : WhhI[j * 256 + (k - 256)];
    g_W_ins[idx] = __float2half_rn(u);
}

__global__ void __launch_bounds__(256)
prep_emb(const float* __restrict__ emb)
{
    int idx = blockIdx.x * 256 + threadIdx.x;
    g_emb_h[idx] = __float2half_rn(emb[idx]);
}

// counting sort by length (descending) + active-count table
__global__ void build_perm(const int* __restrict__ ntok,
                           const int* __restrict__ ninstr)
{
    __shared__ int hist[65];
    __shared__ int off[65];
    if (blockIdx.x == 0) {
        for (int i = threadIdx.x; i < 17; i += blockDim.x) hist[i] = 0;
        __syncthreads();
        for (int i = threadIdx.x; i < NTOK; i += blockDim.x)
            atomicAdd(&hist[ntok[i]], 1);
        __syncthreads();
        if (threadIdx.x == 0) {
            int acc = 0;
            for (int l = 16; l >= 0; --l) { off[l] = acc; acc += hist[l]; }
            for (int t = 0; t < TOKENS; ++t) g_cnt_tok[t] = off[t];
        }
        __syncthreads();
        for (int i = threadIdx.x; i < NTOK; i += blockDim.x) {
            int p = atomicAdd(&off[ntok[i]], 1);
            g_perm_tok[p] = i;
        }
    } else {
        for (int i = threadIdx.x; i < 65; i += blockDim.x) hist[i] = 0;
        __syncthreads();
        for (int i = threadIdx.x; i < BATCH; i += blockDim.x)
            atomicAdd(&hist[ninstr[i]], 1);
        __syncthreads();
        if (threadIdx.x == 0) {
            int acc = 0;
            for (int l = 64; l >= 0; --l) { off[l] = acc; acc += hist[l]; }
            for (int s = 0; s < INSTRS; ++s) g_cnt_ins[s] = off[s];
        }
        __syncthreads();
        for (int i = threadIdx.x; i < BATCH; i += blockDim.x) {
            int p = atomicAdd(&off[ninstr[i]], 1);
            g_perm_ins[p] = i;
        }
    }
}

__global__ void __launch_bounds__(256) zero_state()
{
    int idx = blockIdx.x * 256 + threadIdx.x;
    g_h_tok[0][idx] = __half(0.0f);
    g_h_tok[1][idx] = __half(0.0f);
    g_c_tok[idx]    = 0.0f;
    if (idx < BATCH * HID) {
        g_h_ins[0][idx] = __half(0.0f);
        g_h_ins[1][idx] = __half(0.0f);
        g_c_ins[idx]    = 0.0f;
    }
    if (idx == 0) g_bar = 0u;
}

__global__ void __launch_bounds__(256)
final_linear(const int* __restrict__ ninstr,
             const float* __restrict__ linW,
             const float* __restrict__ linb,
             float* __restrict__ out)
{
    int b = blockIdx.x, tid = threadIdx.x;
    int L = ninstr[b];
    float h = (L > 0) ? __half2float(g_h_ins[(L - 1) & 1][(size_t)b * HID + tid]) : 0.0f;
    float v = h * linW[tid];
#pragma unroll
    for (int o = 16; o > 0; o >>= 1) v += __shfl_down_sync(0xffffffffu, v, o);
    __shared__ float red[8];
    if ((tid & 31) == 0) red[tid >> 5] = v;
    __syncthreads();
    if (tid < 8) {
        float s = red[tid];
#pragma unroll
        for (int o = 4; o > 0; o >>= 1) s += __shfl_down_sync(0xffu, s, o);
        if (tid == 0) out[b] = s + linb[0];
    }
}

extern "C" void kernel_launch(void* const* d_in, const int* in_sizes, int n_in,
                              void* d_out, int out_size)
{
    const int*   blocks = (const int*)d_in[0];
    const int*   ninstr = (const int*)d_in[1];
    const int*   ntok   = (const int*)d_in[2];
    const float* emb    = (const float*)d_in[3];
    const float* WihT   = (const float*)d_in[4];
    const float* WhhT   = (const float*)d_in[5];
    const float* bT     = (const float*)d_in[6];
    const float* WihI   = (const float*)d_in[7];
    const float* WhhI   = (const float*)d_in[8];
    const float* bI     = (const float*)d_in[9];
    const float* linW   = (const float*)d_in[10];
    const float* linb   = (const float*)d_in[11];
    float* out = (float*)d_out;
    (void)in_sizes; (void)n_in; (void)out_size;

    cudaFuncSetAttribute(tok_step,      cudaFuncAttributeMaxDynamicSharedMemorySize, SMEM_TOK);
    cudaFuncSetAttribute(instr_persist, cudaFuncAttributeMaxDynamicSharedMemorySize, SMEM_INS);

    zero_state<<<NTOK * HID / 256, 256>>>();
    build_perm<<<2, 512>>>(ntok, ninstr);
    prep_weights<<<FOURH * KTOT / 256, 256>>>(WihT, WhhT, WihI, WhhI);
    prep_emb<<<4096 * EMB / 256, 256>>>(emb);

    for (int t = 0; t < TOKENS; ++t) {
        dim3 grid(NTOK / BM, FOURH / BN);          // 128 x 16, blocks self-trim
        tok_step<<<grid, 256, SMEM_TOK>>>(t, blocks, bT, ntok);
    }
    gather_tok<<<NTOK * HID / 256, 256>>>(ntok);
    instr_persist<<<INS_BLOCKS, 256, SMEM_INS>>>(bI, ninstr);
    final_linear<<<BATCH, 256>>>(ninstr, linW, linb, out);
}